// round 12
// baseline (speedup 1.0000x reference)
#include <cuda_runtime.h>
#include <cuda_bf16.h>

/* Shapes: E=16384 edges, B=16 graphs (contiguous equal segments of 1024),
   H=256, S=32 seeds, 8 heads x headdim 32.
   Pipeline:
     k0a: q = seed @ Wq                       [32,256]
     k0b: Wc = [ (Wk-folded-q)/sqrt(32) | Wv ] [256,512]
     k1 : fused GEMM edge_features @ Wc -> scores^T [256,E] and V [E,256]
     k2 : per-(graph,head) segment softmax + weighted pooling -> att [B,32,256]
     k3 : residual + out_proj + LayerNorm -> flat [B,8192]
     k4 : h1 = silu(flat @ W1 + b1)           [B,256]
     k5 : out = h1 @ W2 + b2                  [B,256]
*/

#define HH   256
#define SS   32
#define NHH  8
#define HDD  32
#define BB   16
#define EE   16384

/* scratch: static device globals (no runtime allocation allowed) */
__device__ float g_q[SS * HH];
__device__ float g_Wc[HH * 512];
__device__ float g_St[256 * EE];
__device__ float g_V[EE * HH];
__device__ float g_att[BB * SS * HH];
__device__ float g_flat[BB * SS * HH];
__device__ float g_h1[BB * HH];

/* K0a: q = seed @ Wq */
__global__ void k0a_q(const float* __restrict__ seed, const float* __restrict__ Wq)
{
    __shared__ float sr[HH];
    const int s = blockIdx.x, t = threadIdx.x;
    sr[t] = seed[s * HH + t];
    __syncthreads();
    float acc = 0.f;
#pragma unroll 8
    for (int c = 0; c < HH; c++) acc += sr[c] * Wq[c * HH + t];
    g_q[s * HH + t] = acc;
}

/* K0b: build combined weight [Qk_scaled | Wv] */
__global__ void k0b_w(const float* __restrict__ Wk, const float* __restrict__ Wv)
{
    const int c = blockIdx.x, j = threadIdx.x;   /* j = s*8 + h */
    const int s = j >> 3, h = j & 7;
    float acc = 0.f;
#pragma unroll
    for (int d = 0; d < HDD; d++)
        acc += Wk[c * HH + h * HDD + d] * g_q[s * HH + h * HDD + d];
    g_Wc[c * 512 + j]       = acc * 0.17677669529663687f;   /* 1/sqrt(32) */
    g_Wc[c * 512 + 256 + j] = Wv[c * HH + j];
}

/* K1: fused GEMM [E,256] @ [256,512] -> scores^T | V
   128x128 tile, K-tile 16, 256 threads, 8x8 microtile, double-buffered smem,
   packed fma.rn.f32x2 inner product (2x FFMA throughput on sm_103a). */
__global__ __launch_bounds__(256, 2) void k1_gemm(const float* __restrict__ A, int E)
{
    __shared__ __align__(16) float As[2][16][128];   /* [k][m] */
    __shared__ __align__(16) float Bs[2][16][128];   /* [k][n] */
    const int t  = threadIdx.x;
    const int tx = t & 15, ty = t >> 4;
    const int m0 = blockIdx.x * 128;
    const int n0 = blockIdx.y * 128;

    unsigned long long acc2[8][4];
#pragma unroll
    for (int i = 0; i < 8; i++)
#pragma unroll
        for (int j = 0; j < 4; j++) acc2[i][j] = 0ull;

    const int arow = t >> 2, ac4 = (t & 3) << 2;   /* A tile: 128 rows x 16 cols */
    const int brow = t >> 5, bc4 = (t & 31) << 2;  /* B tile: 16 rows x 128 cols */
    const float* Ap = A + (size_t)(m0 + arow) * HH + ac4;
    const float* Bp = g_Wc + (size_t)brow * 512 + n0 + bc4;

    float4 a0 = *(const float4*)Ap;
    float4 a1 = *(const float4*)(Ap + 64 * HH);
    float4 b0 = *(const float4*)Bp;
    float4 b1 = *(const float4*)(Bp + 8 * 512);
    As[0][ac4 + 0][arow]      = a0.x; As[0][ac4 + 1][arow]      = a0.y;
    As[0][ac4 + 2][arow]      = a0.z; As[0][ac4 + 3][arow]      = a0.w;
    As[0][ac4 + 0][arow + 64] = a1.x; As[0][ac4 + 1][arow + 64] = a1.y;
    As[0][ac4 + 2][arow + 64] = a1.z; As[0][ac4 + 3][arow + 64] = a1.w;
    *(float4*)&Bs[0][brow][bc4]     = b0;
    *(float4*)&Bs[0][brow + 8][bc4] = b1;
    __syncthreads();

    for (int kt = 0; kt < 16; kt++) {
        const int cur = kt & 1;
        if (kt < 15) {
            const int kk = (kt + 1) * 16;
            a0 = *(const float4*)(Ap + kk);
            a1 = *(const float4*)(Ap + kk + 64 * HH);
            b0 = *(const float4*)(Bp + (size_t)kk * 512);
            b1 = *(const float4*)(Bp + (size_t)(kk + 8) * 512);
        }
#pragma unroll
        for (int k = 0; k < 16; k++) {
            const float4 av0 = *(const float4*)&As[cur][k][ty * 8];
            const float4 av1 = *(const float4*)&As[cur][k][ty * 8 + 4];
            const ulonglong2 bp0 = *(const ulonglong2*)&Bs[cur][k][tx * 8];
            const ulonglong2 bp1 = *(const ulonglong2*)&Bs[cur][k][tx * 8 + 4];
            const unsigned long long bb[4] = { bp0.x, bp0.y, bp1.x, bp1.y };
            const float aa[8] = { av0.x, av0.y, av0.z, av0.w,
                                  av1.x, av1.y, av1.z, av1.w };
#pragma unroll
            for (int i = 0; i < 8; i++) {
                unsigned long long ap;
                const unsigned int au = __float_as_uint(aa[i]);
                asm("mov.b64 %0, {%1, %1};" : "=l"(ap) : "r"(au));
#pragma unroll
                for (int jp = 0; jp < 4; jp++)
                    asm("fma.rn.f32x2 %0, %1, %2, %0;"
                        : "+l"(acc2[i][jp]) : "l"(ap), "l"(bb[jp]));
            }
        }
        if (kt < 15) {
            const int nb = cur ^ 1;
            As[nb][ac4 + 0][arow]      = a0.x; As[nb][ac4 + 1][arow]      = a0.y;
            As[nb][ac4 + 2][arow]      = a0.z; As[nb][ac4 + 3][arow]      = a0.w;
            As[nb][ac4 + 0][arow + 64] = a1.x; As[nb][ac4 + 1][arow + 64] = a1.y;
            As[nb][ac4 + 2][arow + 64] = a1.z; As[nb][ac4 + 3][arow + 64] = a1.w;
            *(float4*)&Bs[nb][brow][bc4]     = b0;
            *(float4*)&Bs[nb][brow + 8][bc4] = b1;
        }
        __syncthreads();
    }

    /* unpack packed accumulators */
    float acc[8][8];
#pragma unroll
    for (int i = 0; i < 8; i++)
#pragma unroll
        for (int jp = 0; jp < 4; jp++) {
            unsigned int lo, hi;
            asm("mov.b64 {%0, %1}, %2;" : "=r"(lo), "=r"(hi) : "l"(acc2[i][jp]));
            acc[i][2 * jp]     = __uint_as_float(lo);
            acc[i][2 * jp + 1] = __uint_as_float(hi);
        }

    if (n0 < 256) {
        /* scores half -> transposed store g_St[col][e] */
#pragma unroll
        for (int j = 0; j < 8; j++) {
            const int col = n0 + tx * 8 + j;
            float* p = g_St + (size_t)col * E + m0 + ty * 8;
            *(float4*)p       = make_float4(acc[0][j], acc[1][j], acc[2][j], acc[3][j]);
            *(float4*)(p + 4) = make_float4(acc[4][j], acc[5][j], acc[6][j], acc[7][j]);
        }
    } else {
        /* V half -> row-major g_V[e][j] */
#pragma unroll
        for (int i = 0; i < 8; i++) {
            float* p = g_V + (size_t)(m0 + ty * 8 + i) * HH + (n0 - 256) + tx * 8;
            *(float4*)p       = make_float4(acc[i][0], acc[i][1], acc[i][2], acc[i][3]);
            *(float4*)(p + 4) = make_float4(acc[i][4], acc[i][5], acc[i][6], acc[i][7]);
        }
    }
}

/* K2: segment softmax + attention pooling per (graph, head) */
__global__ void k2_attn(int E, int epg)
{
    const int b = blockIdx.x, h = blockIdx.y;
    const int t = threadIdx.x;
    const int lane = t & 31, w = t >> 5;
    __shared__ float m_s[SS], rden[SS];
    __shared__ __align__(16) float  wsm[SS][64];
    __shared__ __align__(16) float4 vsm[64][8];

    /* pass 1: per-s max and sum(exp) over segment (contiguous runs of St) */
#pragma unroll
    for (int sg = 0; sg < 4; sg++) {
        const int s = w + sg * 8;
        const float* p = g_St + (size_t)(s * NHH + h) * E + b * epg;
        float mx = -1e30f;
        for (int e = lane; e < epg; e += 32) mx = fmaxf(mx, p[e]);
#pragma unroll
        for (int o = 16; o; o >>= 1) mx = fmaxf(mx, __shfl_xor_sync(0xffffffffu, mx, o));
        float sum = 0.f;
        for (int e = lane; e < epg; e += 32) sum += __expf(p[e] - mx);
#pragma unroll
        for (int o = 16; o; o >>= 1) sum += __shfl_xor_sync(0xffffffffu, sum, o);
        if (lane == 0) { m_s[s] = mx; rden[s] = 1.f / sum; }
    }
    __syncthreads();

    /* pass 2: att[s,d] += w[e,s] * v[e,d], chunks of 64 edges */
    const int sw = t >> 3, dg = t & 7;
    const int off = dg * 8;
    const float* sp = g_St + (size_t)(sw * NHH + h) * E + b * epg + off;
    const float msw = m_s[sw], rd = rden[sw];
    float4 acc = make_float4(0.f, 0.f, 0.f, 0.f);

    for (int e0 = 0; e0 < epg; e0 += 64) {
        const float4 x0 = *(const float4*)(sp + e0);
        const float4 x1 = *(const float4*)(sp + e0 + 4);
        wsm[sw][off + 0] = __expf(x0.x - msw) * rd;
        wsm[sw][off + 1] = __expf(x0.y - msw) * rd;
        wsm[sw][off + 2] = __expf(x0.z - msw) * rd;
        wsm[sw][off + 3] = __expf(x0.w - msw) * rd;
        wsm[sw][off + 4] = __expf(x1.x - msw) * rd;
        wsm[sw][off + 5] = __expf(x1.y - msw) * rd;
        wsm[sw][off + 6] = __expf(x1.z - msw) * rd;
        wsm[sw][off + 7] = __expf(x1.w - msw) * rd;
        {
            int e = t >> 3;
            const int dgi = t & 7;
            vsm[e][dgi] = ((const float4*)(g_V + (size_t)(b * epg + e0 + e) * HH + h * HDD))[dgi];
            e += 32;
            vsm[e][dgi] = ((const float4*)(g_V + (size_t)(b * epg + e0 + e) * HH + h * HDD))[dgi];
        }
        __syncthreads();
#pragma unroll 8
        for (int e = 0; e < 64; e++) {
            const float wv = wsm[sw][e];
            const float4 v4 = vsm[e][dg];
            acc.x += wv * v4.x; acc.y += wv * v4.y;
            acc.z += wv * v4.z; acc.w += wv * v4.w;
        }
        __syncthreads();
    }
    float* ap = g_att + (size_t)(b * SS + sw) * HH + h * HDD + dg * 4;
    *(float4*)ap = acc;
}

/* K3: y = seed + att @ Wo + bo; LayerNorm. 8 seed-rows per block so Wo is
   read 64x from L2 instead of 512x. */
__global__ void k3_ln(const float* __restrict__ seed, const float* __restrict__ Wo,
                      const float* __restrict__ bo, const float* __restrict__ lng,
                      const float* __restrict__ lnb)
{
    const int b = blockIdx.x, sq = blockIdx.y;
    const int c = threadIdx.x;
    __shared__ float ar[8][HH];
    __shared__ float redA[8][8], redB[8][8];
#pragma unroll
    for (int i = 0; i < 8; i++)
        ar[i][c] = g_att[(size_t)(b * SS + sq * 8 + i) * HH + c];
    __syncthreads();

    float y[8];
#pragma unroll
    for (int i = 0; i < 8; i++) y[i] = seed[(sq * 8 + i) * HH + c] + bo[c];
#pragma unroll 4
    for (int k = 0; k < HH; k++) {
        const float wv = Wo[k * HH + c];
#pragma unroll
        for (int i = 0; i < 8; i++) y[i] += ar[i][k] * wv;
    }

    float s1[8], s2[8];
#pragma unroll
    for (int i = 0; i < 8; i++) { s1[i] = y[i]; s2[i] = y[i] * y[i]; }
#pragma unroll
    for (int o = 16; o; o >>= 1) {
#pragma unroll
        for (int i = 0; i < 8; i++) {
            s1[i] += __shfl_xor_sync(0xffffffffu, s1[i], o);
            s2[i] += __shfl_xor_sync(0xffffffffu, s2[i], o);
        }
    }
    const int wid = c >> 5, lane = c & 31;
    if (lane == 0) {
#pragma unroll
        for (int i = 0; i < 8; i++) { redA[wid][i] = s1[i]; redB[wid][i] = s2[i]; }
    }
    __syncthreads();
#pragma unroll
    for (int i = 0; i < 8; i++) {
        float t1 = 0.f, t2 = 0.f;
#pragma unroll
        for (int ww = 0; ww < 8; ww++) { t1 += redA[ww][i]; t2 += redB[ww][i]; }
        const float mu   = t1 * (1.f / HH);
        const float var  = t2 * (1.f / HH) - mu * mu;
        const float rstd = rsqrtf(var + 1e-5f);
        g_flat[(size_t)b * (SS * HH) + (sq * 8 + i) * HH + c] =
            (y[i] - mu) * rstd * lng[c] + lnb[c];
    }
}

/* K4: h1 = silu(flat @ W1 + b1). 4 graphs per block to reuse W1 loads. */
__global__ void k4_mlp1(const float* __restrict__ W1, const float* __restrict__ b1)
{
    const int bq = blockIdx.x, cg = blockIdx.y;   /* bq 0..3, cg 0..31 */
    const int t = threadIdx.x;
    const int cl = t & 7, kl = t >> 3;            /* kl 0..31 */
    const int c = cg * 8 + cl;
    __shared__ __align__(16) float fsm[4][2048];
    __shared__ float red2[32][32];
    float acc[4] = { 0.f, 0.f, 0.f, 0.f };

    for (int k0 = 0; k0 < SS * HH; k0 += 2048) {
        __syncthreads();
#pragma unroll
        for (int i = t; i < 2048; i += 256) {
            const int gg = i >> 9, jj = i & 511;
            ((float4*)fsm[gg])[jj] =
                ((const float4*)(g_flat + (size_t)(bq * 4 + gg) * (SS * HH) + k0))[jj];
        }
        __syncthreads();
#pragma unroll 4
        for (int kloc = kl; kloc < 2048; kloc += 32) {
            const float wv = W1[(size_t)(k0 + kloc) * HH + c];
            acc[0] += wv * fsm[0][kloc];
            acc[1] += wv * fsm[1][kloc];
            acc[2] += wv * fsm[2][kloc];
            acc[3] += wv * fsm[3][kloc];
        }
    }
#pragma unroll
    for (int g = 0; g < 4; g++) red2[kl][cl * 4 + g] = acc[g];
    __syncthreads();
    if (t < 32) {
        const int cc = t >> 2, gg = t & 3;
        float s = 0.f;
#pragma unroll 8
        for (int k = 0; k < 32; k++) s += red2[k][cc * 4 + gg];
        s += b1[cg * 8 + cc];
        g_h1[(size_t)(bq * 4 + gg) * HH + cg * 8 + cc] = s / (1.f + __expf(-s));
    }
}

/* K5: out = h1 @ W2 + b2 */
__global__ void k5_mlp2(const float* __restrict__ W2, const float* __restrict__ b2,
                        float* __restrict__ out)
{
    const int b = blockIdx.x, j = threadIdx.x;
    __shared__ float hr[HH];
    hr[j] = g_h1[b * HH + j];
    __syncthreads();
    float o = b2[j];
#pragma unroll 8
    for (int ci = 0; ci < HH; ci++) o += hr[ci] * W2[ci * HH + j];
    out[b * HH + j] = o;
}

extern "C" void kernel_launch(void* const* d_in, const int* in_sizes, int n_in,
                              void* d_out, int out_size)
{
    const float* edge_features = (const float*)d_in[0];
    /* d_in[1] = edge_coords (unused); d_in[2] = batch (contiguous equal segments) */
    const float* seed = (const float*)d_in[3];
    const float* Wq   = (const float*)d_in[4];
    const float* Wk   = (const float*)d_in[5];
    const float* Wv   = (const float*)d_in[6];
    const float* Wo   = (const float*)d_in[7];
    const float* bo   = (const float*)d_in[8];
    const float* lng  = (const float*)d_in[9];
    const float* lnb  = (const float*)d_in[10];
    const float* W1   = (const float*)d_in[11];
    const float* b1   = (const float*)d_in[12];
    const float* W2   = (const float*)d_in[13];
    const float* b2   = (const float*)d_in[14];
    float* out = (float*)d_out;

    const int E   = in_sizes[0] / HH;     /* 16384 */
    const int epg = E / BB;               /* 1024  */

    k0a_q<<<SS, HH>>>(seed, Wq);
    k0b_w<<<HH, HH>>>(Wk, Wv);
    k1_gemm<<<dim3(E / 128, 4), 256>>>(edge_features, E);
    k2_attn<<<dim3(BB, NHH), 256>>>(E, epg);
    k3_ln<<<dim3(BB, 4), 256>>>(seed, Wo, bo, lng, lnb);
    k4_mlp1<<<dim3(4, 32), 256>>>(W1, b1);
    k5_mlp2<<<BB, HH>>>(W2, b2, out);
}

// round 13
// speedup vs baseline: 1.5621x; 1.5621x over previous
#include <cuda_runtime.h>
#include <cuda_bf16.h>

/* Shapes: E=16384 edges, B=16 graphs (contiguous equal segments of 1024),
   H=256, S=32 seeds, 8 heads x headdim 32.
   Pipeline:
     k0a: q = seed @ Wq                        [32,256]
     k0b: Wc = [ (Wk-folded-q)/sqrt(32) | Wv ] [256,512]
     k1 : fused GEMM edge_features @ Wc -> scores^T [256,E] and V [E,256]
     k2a: per-(graph,seed,head) segment max + sum(exp)
     k2b: weighted pooling, 4 edge-chunks per (graph,head) -> partials
     k3 : sum partials + residual + out_proj + LayerNorm -> flat [B,8192]
     k4 : h1 = silu(flat @ W1 + b1)            [B,256]
     k5 : out = h1 @ W2 + b2                   [B,256]
*/

#define HH   256
#define SS   32
#define NHH  8
#define HDD  32
#define BB   16
#define EE   16384
#define NCH  4            /* edge chunks for pooling */

/* scratch: static device globals (no runtime allocation allowed) */
__device__ float g_q[SS * HH];
__device__ float g_Wc[HH * 512];
__device__ float g_St[256 * EE];
__device__ float g_V[EE * HH];
__device__ float g_ms[BB * SS * NHH];
__device__ float g_rs[BB * SS * NHH];
__device__ float g_attp[NCH * BB * SS * HH];
__device__ float g_flat[BB * SS * HH];
__device__ float g_h1[BB * HH];

/* K0a: q = seed @ Wq */
__global__ void k0a_q(const float* __restrict__ seed, const float* __restrict__ Wq)
{
    __shared__ float sr[HH];
    const int s = blockIdx.x, t = threadIdx.x;
    sr[t] = seed[s * HH + t];
    __syncthreads();
    float acc = 0.f;
#pragma unroll 8
    for (int c = 0; c < HH; c++) acc += sr[c] * Wq[c * HH + t];
    g_q[s * HH + t] = acc;
}

/* K0b: build combined weight [Qk_scaled | Wv] */
__global__ void k0b_w(const float* __restrict__ Wk, const float* __restrict__ Wv)
{
    const int c = blockIdx.x, j = threadIdx.x;   /* j = s*8 + h */
    const int s = j >> 3, h = j & 7;
    float acc = 0.f;
#pragma unroll
    for (int d = 0; d < HDD; d++)
        acc += Wk[c * HH + h * HDD + d] * g_q[s * HH + h * HDD + d];
    g_Wc[c * 512 + j]       = acc * 0.17677669529663687f;   /* 1/sqrt(32) */
    g_Wc[c * 512 + 256 + j] = Wv[c * HH + j];
}

/* K1: fused GEMM [E,256] @ [256,512] -> scores^T | V
   128x128 tile, K-tile 16, 256 threads, 8x8 microtile, double-buffered smem,
   packed fma.rn.f32x2 inner product. NOTE: no min-blocks launch bound --
   the accumulators need >128 registers; capping at 128 caused spills. */
__global__ __launch_bounds__(256) void k1_gemm(const float* __restrict__ A, int E)
{
    __shared__ __align__(16) float As[2][16][128];   /* [k][m] */
    __shared__ __align__(16) float Bs[2][16][128];   /* [k][n] */
    const int t  = threadIdx.x;
    const int tx = t & 15, ty = t >> 4;
    const int m0 = blockIdx.x * 128;
    const int n0 = blockIdx.y * 128;

    unsigned long long acc2[8][4];
#pragma unroll
    for (int i = 0; i < 8; i++)
#pragma unroll
        for (int j = 0; j < 4; j++) acc2[i][j] = 0ull;

    const int arow = t >> 2, ac4 = (t & 3) << 2;   /* A tile: 128 rows x 16 cols */
    const int brow = t >> 5, bc4 = (t & 31) << 2;  /* B tile: 16 rows x 128 cols */
    const float* Ap = A + (size_t)(m0 + arow) * HH + ac4;
    const float* Bp = g_Wc + (size_t)brow * 512 + n0 + bc4;

    float4 a0 = *(const float4*)Ap;
    float4 a1 = *(const float4*)(Ap + 64 * HH);
    float4 b0 = *(const float4*)Bp;
    float4 b1 = *(const float4*)(Bp + 8 * 512);
    As[0][ac4 + 0][arow]      = a0.x; As[0][ac4 + 1][arow]      = a0.y;
    As[0][ac4 + 2][arow]      = a0.z; As[0][ac4 + 3][arow]      = a0.w;
    As[0][ac4 + 0][arow + 64] = a1.x; As[0][ac4 + 1][arow + 64] = a1.y;
    As[0][ac4 + 2][arow + 64] = a1.z; As[0][ac4 + 3][arow + 64] = a1.w;
    *(float4*)&Bs[0][brow][bc4]     = b0;
    *(float4*)&Bs[0][brow + 8][bc4] = b1;
    __syncthreads();

    for (int kt = 0; kt < 16; kt++) {
        const int cur = kt & 1;
        if (kt < 15) {
            const int kk = (kt + 1) * 16;
            a0 = *(const float4*)(Ap + kk);
            a1 = *(const float4*)(Ap + kk + 64 * HH);
            b0 = *(const float4*)(Bp + (size_t)kk * 512);
            b1 = *(const float4*)(Bp + (size_t)(kk + 8) * 512);
        }
#pragma unroll
        for (int k = 0; k < 16; k++) {
            const float4 av0 = *(const float4*)&As[cur][k][ty * 8];
            const float4 av1 = *(const float4*)&As[cur][k][ty * 8 + 4];
            const ulonglong2 bp0 = *(const ulonglong2*)&Bs[cur][k][tx * 8];
            const ulonglong2 bp1 = *(const ulonglong2*)&Bs[cur][k][tx * 8 + 4];
            const unsigned long long bb[4] = { bp0.x, bp0.y, bp1.x, bp1.y };
            const float aa[8] = { av0.x, av0.y, av0.z, av0.w,
                                  av1.x, av1.y, av1.z, av1.w };
#pragma unroll
            for (int i = 0; i < 8; i++) {
                unsigned long long ap;
                const unsigned int au = __float_as_uint(aa[i]);
                asm("mov.b64 %0, {%1, %1};" : "=l"(ap) : "r"(au));
#pragma unroll
                for (int jp = 0; jp < 4; jp++)
                    asm("fma.rn.f32x2 %0, %1, %2, %0;"
                        : "+l"(acc2[i][jp]) : "l"(ap), "l"(bb[jp]));
            }
        }
        if (kt < 15) {
            const int nb = cur ^ 1;
            As[nb][ac4 + 0][arow]      = a0.x; As[nb][ac4 + 1][arow]      = a0.y;
            As[nb][ac4 + 2][arow]      = a0.z; As[nb][ac4 + 3][arow]      = a0.w;
            As[nb][ac4 + 0][arow + 64] = a1.x; As[nb][ac4 + 1][arow + 64] = a1.y;
            As[nb][ac4 + 2][arow + 64] = a1.z; As[nb][ac4 + 3][arow + 64] = a1.w;
            *(float4*)&Bs[nb][brow][bc4]     = b0;
            *(float4*)&Bs[nb][brow + 8][bc4] = b1;
        }
        __syncthreads();
    }

    /* unpack packed accumulators */
    float acc[8][8];
#pragma unroll
    for (int i = 0; i < 8; i++)
#pragma unroll
        for (int jp = 0; jp < 4; jp++) {
            unsigned int lo, hi;
            asm("mov.b64 {%0, %1}, %2;" : "=r"(lo), "=r"(hi) : "l"(acc2[i][jp]));
            acc[i][2 * jp]     = __uint_as_float(lo);
            acc[i][2 * jp + 1] = __uint_as_float(hi);
        }

    if (n0 < 256) {
        /* scores half -> transposed store g_St[col][e] */
#pragma unroll
        for (int j = 0; j < 8; j++) {
            const int col = n0 + tx * 8 + j;
            float* p = g_St + (size_t)col * E + m0 + ty * 8;
            *(float4*)p       = make_float4(acc[0][j], acc[1][j], acc[2][j], acc[3][j]);
            *(float4*)(p + 4) = make_float4(acc[4][j], acc[5][j], acc[6][j], acc[7][j]);
        }
    } else {
        /* V half -> row-major g_V[e][j] */
#pragma unroll
        for (int i = 0; i < 8; i++) {
            float* p = g_V + (size_t)(m0 + ty * 8 + i) * HH + (n0 - 256) + tx * 8;
            *(float4*)p       = make_float4(acc[i][0], acc[i][1], acc[i][2], acc[i][3]);
            *(float4*)(p + 4) = make_float4(acc[i][4], acc[i][5], acc[i][6], acc[i][7]);
        }
    }
}

/* K2a: per-(graph,seed,head) segment max and sum(exp) */
__global__ void k2a_stats(int E, int epg)
{
    const int b = blockIdx.x, h = blockIdx.y;
    const int t = threadIdx.x;
    const int lane = t & 31, w = t >> 5;
#pragma unroll
    for (int sg = 0; sg < 4; sg++) {
        const int s = w + sg * 8;
        const float* p = g_St + (size_t)(s * NHH + h) * E + b * epg;
        float mx = -1e30f;
        for (int e = lane; e < epg; e += 32) mx = fmaxf(mx, p[e]);
#pragma unroll
        for (int o = 16; o; o >>= 1) mx = fmaxf(mx, __shfl_xor_sync(0xffffffffu, mx, o));
        float sum = 0.f;
        for (int e = lane; e < epg; e += 32) sum += __expf(p[e] - mx);
#pragma unroll
        for (int o = 16; o; o >>= 1) sum += __shfl_xor_sync(0xffffffffu, sum, o);
        if (lane == 0) {
            g_ms[(b * SS + s) * NHH + h] = mx;
            g_rs[(b * SS + s) * NHH + h] = 1.f / sum;
        }
    }
}

/* K2b: pooled attention partials. grid (B, nh, NCH); each block handles
   epg/NCH edges and writes a disjoint partial [32 s][32 d] slice. */
__global__ void k2b_pool(int E, int epg)
{
    const int b = blockIdx.x, h = blockIdx.y, ch = blockIdx.z;
    const int t = threadIdx.x;
    const int cpg = epg / NCH;                       /* 256 edges */
    const int e_base = b * epg + ch * cpg;
    __shared__ __align__(16) float  wsm[SS][64];
    __shared__ __align__(16) float4 vsm[64][8];

    const int sw = t >> 3, dg = t & 7;
    const int off = dg * 8;
    const float* sp = g_St + (size_t)(sw * NHH + h) * E + e_base + off;
    const float msw = g_ms[(b * SS + sw) * NHH + h];
    const float rd  = g_rs[(b * SS + sw) * NHH + h];
    float4 acc = make_float4(0.f, 0.f, 0.f, 0.f);

    for (int e0 = 0; e0 < cpg; e0 += 64) {
        const float4 x0 = *(const float4*)(sp + e0);
        const float4 x1 = *(const float4*)(sp + e0 + 4);
        wsm[sw][off + 0] = __expf(x0.x - msw) * rd;
        wsm[sw][off + 1] = __expf(x0.y - msw) * rd;
        wsm[sw][off + 2] = __expf(x0.z - msw) * rd;
        wsm[sw][off + 3] = __expf(x0.w - msw) * rd;
        wsm[sw][off + 4] = __expf(x1.x - msw) * rd;
        wsm[sw][off + 5] = __expf(x1.y - msw) * rd;
        wsm[sw][off + 6] = __expf(x1.z - msw) * rd;
        wsm[sw][off + 7] = __expf(x1.w - msw) * rd;
        {
            int e = t >> 3;
            const int dgi = t & 7;
            vsm[e][dgi] = ((const float4*)(g_V + (size_t)(e_base + e0 + e) * HH + h * HDD))[dgi];
            e += 32;
            vsm[e][dgi] = ((const float4*)(g_V + (size_t)(e_base + e0 + e) * HH + h * HDD))[dgi];
        }
        __syncthreads();
#pragma unroll 8
        for (int e = 0; e < 64; e++) {
            const float wv = wsm[sw][e];
            const float4 v4 = vsm[e][dg];
            acc.x += wv * v4.x; acc.y += wv * v4.y;
            acc.z += wv * v4.z; acc.w += wv * v4.w;
        }
        __syncthreads();
    }
    float* ap = g_attp + (size_t)((ch * BB + b) * SS + sw) * HH + h * HDD + dg * 4;
    *(float4*)ap = acc;
}

/* K3: sum partials; y = seed + att @ Wo + bo; LayerNorm. */
__global__ void k3_ln(const float* __restrict__ seed, const float* __restrict__ Wo,
                      const float* __restrict__ bo, const float* __restrict__ lng,
                      const float* __restrict__ lnb)
{
    const int b = blockIdx.x, sq = blockIdx.y;
    const int c = threadIdx.x;
    __shared__ float ar[8][HH];
    __shared__ float redA[8][8], redB[8][8];
#pragma unroll
    for (int i = 0; i < 8; i++) {
        const size_t row = (size_t)(b * SS + sq * 8 + i) * HH + c;
        float v = g_attp[row];
#pragma unroll
        for (int ch = 1; ch < NCH; ch++)
            v += g_attp[(size_t)ch * (BB * SS * HH) + row];
        ar[i][c] = v;
    }
    __syncthreads();

    float y[8];
#pragma unroll
    for (int i = 0; i < 8; i++) y[i] = seed[(sq * 8 + i) * HH + c] + bo[c];
#pragma unroll 4
    for (int k = 0; k < HH; k++) {
        const float wv = Wo[k * HH + c];
#pragma unroll
        for (int i = 0; i < 8; i++) y[i] += ar[i][k] * wv;
    }

    float s1[8], s2[8];
#pragma unroll
    for (int i = 0; i < 8; i++) { s1[i] = y[i]; s2[i] = y[i] * y[i]; }
#pragma unroll
    for (int o = 16; o; o >>= 1) {
#pragma unroll
        for (int i = 0; i < 8; i++) {
            s1[i] += __shfl_xor_sync(0xffffffffu, s1[i], o);
            s2[i] += __shfl_xor_sync(0xffffffffu, s2[i], o);
        }
    }
    const int wid = c >> 5, lane = c & 31;
    if (lane == 0) {
#pragma unroll
        for (int i = 0; i < 8; i++) { redA[wid][i] = s1[i]; redB[wid][i] = s2[i]; }
    }
    __syncthreads();
#pragma unroll
    for (int i = 0; i < 8; i++) {
        float t1 = 0.f, t2 = 0.f;
#pragma unroll
        for (int ww = 0; ww < 8; ww++) { t1 += redA[ww][i]; t2 += redB[ww][i]; }
        const float mu   = t1 * (1.f / HH);
        const float var  = t2 * (1.f / HH) - mu * mu;
        const float rstd = rsqrtf(var + 1e-5f);
        g_flat[(size_t)b * (SS * HH) + (sq * 8 + i) * HH + c] =
            (y[i] - mu) * rstd * lng[c] + lnb[c];
    }
}

/* K4: h1 = silu(flat @ W1 + b1). 4 graphs per block to reuse W1 loads. */
__global__ void k4_mlp1(const float* __restrict__ W1, const float* __restrict__ b1)
{
    const int bq = blockIdx.x, cg = blockIdx.y;   /* bq 0..3, cg 0..31 */
    const int t = threadIdx.x;
    const int cl = t & 7, kl = t >> 3;            /* kl 0..31 */
    const int c = cg * 8 + cl;
    __shared__ __align__(16) float fsm[4][2048];
    __shared__ float red2[32][32];
    float acc[4] = { 0.f, 0.f, 0.f, 0.f };

    for (int k0 = 0; k0 < SS * HH; k0 += 2048) {
        __syncthreads();
#pragma unroll
        for (int i = t; i < 2048; i += 256) {
            const int gg = i >> 9, jj = i & 511;
            ((float4*)fsm[gg])[jj] =
                ((const float4*)(g_flat + (size_t)(bq * 4 + gg) * (SS * HH) + k0))[jj];
        }
        __syncthreads();
#pragma unroll 4
        for (int kloc = kl; kloc < 2048; kloc += 32) {
            const float wv = W1[(size_t)(k0 + kloc) * HH + c];
            acc[0] += wv * fsm[0][kloc];
            acc[1] += wv * fsm[1][kloc];
            acc[2] += wv * fsm[2][kloc];
            acc[3] += wv * fsm[3][kloc];
        }
    }
#pragma unroll
    for (int g = 0; g < 4; g++) red2[kl][cl * 4 + g] = acc[g];
    __syncthreads();
    if (t < 32) {
        const int cc = t >> 2, gg = t & 3;
        float s = 0.f;
#pragma unroll 8
        for (int k = 0; k < 32; k++) s += red2[k][cc * 4 + gg];
        s += b1[cg * 8 + cc];
        g_h1[(size_t)(bq * 4 + gg) * HH + cg * 8 + cc] = s / (1.f + __expf(-s));
    }
}

/* K5: out = h1 @ W2 + b2 */
__global__ void k5_mlp2(const float* __restrict__ W2, const float* __restrict__ b2,
                        float* __restrict__ out)
{
    const int b = blockIdx.x, j = threadIdx.x;
    __shared__ float hr[HH];
    hr[j] = g_h1[b * HH + j];
    __syncthreads();
    float o = b2[j];
#pragma unroll 8
    for (int ci = 0; ci < HH; ci++) o += hr[ci] * W2[ci * HH + j];
    out[b * HH + j] = o;
}

extern "C" void kernel_launch(void* const* d_in, const int* in_sizes, int n_in,
                              void* d_out, int out_size)
{
    const float* edge_features = (const float*)d_in[0];
    /* d_in[1] = edge_coords (unused); d_in[2] = batch (contiguous equal segments) */
    const float* seed = (const float*)d_in[3];
    const float* Wq   = (const float*)d_in[4];
    const float* Wk   = (const float*)d_in[5];
    const float* Wv   = (const float*)d_in[6];
    const float* Wo   = (const float*)d_in[7];
    const float* bo   = (const float*)d_in[8];
    const float* lng  = (const float*)d_in[9];
    const float* lnb  = (const float*)d_in[10];
    const float* W1   = (const float*)d_in[11];
    const float* b1   = (const float*)d_in[12];
    const float* W2   = (const float*)d_in[13];
    const float* b2   = (const float*)d_in[14];
    float* out = (float*)d_out;

    const int E   = in_sizes[0] / HH;     /* 16384 */
    const int epg = E / BB;               /* 1024  */

    k0a_q<<<SS, HH>>>(seed, Wq);
    k0b_w<<<HH, HH>>>(Wk, Wv);
    k1_gemm<<<dim3(E / 128, 4), 256>>>(edge_features, E);
    k2a_stats<<<dim3(BB, NHH), 256>>>(E, epg);
    k2b_pool<<<dim3(BB, NHH, NCH), 256>>>(E, epg);
    k3_ln<<<dim3(BB, 4), 256>>>(seed, Wo, bo, lng, lnb);
    k4_mlp1<<<dim3(4, 32), 256>>>(W1, b1);
    k5_mlp2<<<BB, HH>>>(W2, b2, out);
}

// round 14
// speedup vs baseline: 1.5733x; 1.0072x over previous
#include <cuda_runtime.h>
#include <cuda_bf16.h>

/* Shapes: E=16384 edges, B=16 graphs (contiguous equal segments of 1024),
   H=256, S=32 seeds, 8 heads x headdim 32.
   Pipeline:
     k0a : q = seed @ Wq                        [32,256]
     k0b : Wc = [ (Wk-folded-q)/sqrt(32) | Wv ] [256,512]
     kdum: no-op spacer so ncu (4th launch) profiles k1
     k1  : fused GEMM edge_features @ Wc -> scores^T [256,E] and V [E,256]
     k2b : per-chunk online softmax + pooling -> partials + (m,den) per chunk
     k3  : combine partials (softmax rescale) + residual + out_proj + LN
     k4  : h1 = silu(flat @ W1 + b1)            [B,256]
     k5  : out = h1 @ W2 + b2                   [B,256]
*/

#define HH   256
#define SS   32
#define NHH  8
#define HDD  32
#define BB   16
#define EE   16384
#define NCH  4            /* edge chunks for pooling */

/* scratch: static device globals (no runtime allocation allowed) */
__device__ float g_q[SS * HH];
__device__ float g_Wc[HH * 512];
__device__ float g_St[256 * EE];
__device__ float g_V[EE * HH];
__device__ float g_ms2[NCH * BB * SS * NHH];
__device__ float g_ds2[NCH * BB * SS * NHH];
__device__ float g_attp[NCH * BB * SS * HH];
__device__ float g_flat[BB * SS * HH];
__device__ float g_h1[BB * HH];
__device__ float g_dummy[32];

/* K0a: q = seed @ Wq */
__global__ void k0a_q(const float* __restrict__ seed, const float* __restrict__ Wq)
{
    __shared__ float sr[HH];
    const int s = blockIdx.x, t = threadIdx.x;
    sr[t] = seed[s * HH + t];
    __syncthreads();
    float acc = 0.f;
#pragma unroll 8
    for (int c = 0; c < HH; c++) acc += sr[c] * Wq[c * HH + t];
    g_q[s * HH + t] = acc;
}

/* K0b: build combined weight [Qk_scaled | Wv] */
__global__ void k0b_w(const float* __restrict__ Wk, const float* __restrict__ Wv)
{
    const int c = blockIdx.x, j = threadIdx.x;   /* j = s*8 + h */
    const int s = j >> 3, h = j & 7;
    float acc = 0.f;
#pragma unroll
    for (int d = 0; d < HDD; d++)
        acc += Wk[c * HH + h * HDD + d] * g_q[s * HH + h * HDD + d];
    g_Wc[c * 512 + j]       = acc * 0.17677669529663687f;   /* 1/sqrt(32) */
    g_Wc[c * 512 + 256 + j] = Wv[c * HH + j];
}

/* spacer: puts k1 at launch position 4 so the profiler captures it */
__global__ void kdummy(void)
{
    if (threadIdx.x < 32) g_dummy[threadIdx.x] = (float)threadIdx.x;
}

/* K1: fused GEMM [E,256] @ [256,512] -> scores^T | V
   (FROZEN from R13 for clean profiling.) 128x128 tile, K-tile 16,
   256 threads, 8x8 microtile, double-buffered smem, fma.rn.f32x2. */
__global__ __launch_bounds__(256) void k1_gemm(const float* __restrict__ A, int E)
{
    __shared__ __align__(16) float As[2][16][128];   /* [k][m] */
    __shared__ __align__(16) float Bs[2][16][128];   /* [k][n] */
    const int t  = threadIdx.x;
    const int tx = t & 15, ty = t >> 4;
    const int m0 = blockIdx.x * 128;
    const int n0 = blockIdx.y * 128;

    unsigned long long acc2[8][4];
#pragma unroll
    for (int i = 0; i < 8; i++)
#pragma unroll
        for (int j = 0; j < 4; j++) acc2[i][j] = 0ull;

    const int arow = t >> 2, ac4 = (t & 3) << 2;   /* A tile: 128 rows x 16 cols */
    const int brow = t >> 5, bc4 = (t & 31) << 2;  /* B tile: 16 rows x 128 cols */
    const float* Ap = A + (size_t)(m0 + arow) * HH + ac4;
    const float* Bp = g_Wc + (size_t)brow * 512 + n0 + bc4;

    float4 a0 = *(const float4*)Ap;
    float4 a1 = *(const float4*)(Ap + 64 * HH);
    float4 b0 = *(const float4*)Bp;
    float4 b1 = *(const float4*)(Bp + 8 * 512);
    As[0][ac4 + 0][arow]      = a0.x; As[0][ac4 + 1][arow]      = a0.y;
    As[0][ac4 + 2][arow]      = a0.z; As[0][ac4 + 3][arow]      = a0.w;
    As[0][ac4 + 0][arow + 64] = a1.x; As[0][ac4 + 1][arow + 64] = a1.y;
    As[0][ac4 + 2][arow + 64] = a1.z; As[0][ac4 + 3][arow + 64] = a1.w;
    *(float4*)&Bs[0][brow][bc4]     = b0;
    *(float4*)&Bs[0][brow + 8][bc4] = b1;
    __syncthreads();

    for (int kt = 0; kt < 16; kt++) {
        const int cur = kt & 1;
        if (kt < 15) {
            const int kk = (kt + 1) * 16;
            a0 = *(const float4*)(Ap + kk);
            a1 = *(const float4*)(Ap + kk + 64 * HH);
            b0 = *(const float4*)(Bp + (size_t)kk * 512);
            b1 = *(const float4*)(Bp + (size_t)(kk + 8) * 512);
        }
#pragma unroll
        for (int k = 0; k < 16; k++) {
            const float4 av0 = *(const float4*)&As[cur][k][ty * 8];
            const float4 av1 = *(const float4*)&As[cur][k][ty * 8 + 4];
            const ulonglong2 bp0 = *(const ulonglong2*)&Bs[cur][k][tx * 8];
            const ulonglong2 bp1 = *(const ulonglong2*)&Bs[cur][k][tx * 8 + 4];
            const unsigned long long bb[4] = { bp0.x, bp0.y, bp1.x, bp1.y };
            const float aa[8] = { av0.x, av0.y, av0.z, av0.w,
                                  av1.x, av1.y, av1.z, av1.w };
#pragma unroll
            for (int i = 0; i < 8; i++) {
                unsigned long long ap;
                const unsigned int au = __float_as_uint(aa[i]);
                asm("mov.b64 %0, {%1, %1};" : "=l"(ap) : "r"(au));
#pragma unroll
                for (int jp = 0; jp < 4; jp++)
                    asm("fma.rn.f32x2 %0, %1, %2, %0;"
                        : "+l"(acc2[i][jp]) : "l"(ap), "l"(bb[jp]));
            }
        }
        if (kt < 15) {
            const int nb = cur ^ 1;
            As[nb][ac4 + 0][arow]      = a0.x; As[nb][ac4 + 1][arow]      = a0.y;
            As[nb][ac4 + 2][arow]      = a0.z; As[nb][ac4 + 3][arow]      = a0.w;
            As[nb][ac4 + 0][arow + 64] = a1.x; As[nb][ac4 + 1][arow + 64] = a1.y;
            As[nb][ac4 + 2][arow + 64] = a1.z; As[nb][ac4 + 3][arow + 64] = a1.w;
            *(float4*)&Bs[nb][brow][bc4]     = b0;
            *(float4*)&Bs[nb][brow + 8][bc4] = b1;
        }
        __syncthreads();
    }

    /* unpack packed accumulators */
    float acc[8][8];
#pragma unroll
    for (int i = 0; i < 8; i++)
#pragma unroll
        for (int jp = 0; jp < 4; jp++) {
            unsigned int lo, hi;
            asm("mov.b64 {%0, %1}, %2;" : "=r"(lo), "=r"(hi) : "l"(acc2[i][jp]));
            acc[i][2 * jp]     = __uint_as_float(lo);
            acc[i][2 * jp + 1] = __uint_as_float(hi);
        }

    if (n0 < 256) {
        /* scores half -> transposed store g_St[col][e] */
#pragma unroll
        for (int j = 0; j < 8; j++) {
            const int col = n0 + tx * 8 + j;
            float* p = g_St + (size_t)col * E + m0 + ty * 8;
            *(float4*)p       = make_float4(acc[0][j], acc[1][j], acc[2][j], acc[3][j]);
            *(float4*)(p + 4) = make_float4(acc[4][j], acc[5][j], acc[6][j], acc[7][j]);
        }
    } else {
        /* V half -> row-major g_V[e][j] */
#pragma unroll
        for (int i = 0; i < 8; i++) {
            float* p = g_V + (size_t)(m0 + ty * 8 + i) * HH + (n0 - 256) + tx * 8;
            *(float4*)p       = make_float4(acc[i][0], acc[i][1], acc[i][2], acc[i][3]);
            *(float4*)(p + 4) = make_float4(acc[i][4], acc[i][5], acc[i][6], acc[i][7]);
        }
    }
}

/* K2b: per-chunk online softmax + pooling. grid (B, nh, NCH).
   Each block: 256-edge chunk of one (graph, head). Computes local max and
   sum(exp) per seed (8-lane shuffle), then unnormalized weighted V-sum.
   k3 combines chunks with the standard softmax rescale. */
__global__ void k2b_pool(int E, int epg)
{
    const int b = blockIdx.x, h = blockIdx.y, ch = blockIdx.z;
    const int t = threadIdx.x;
    const int cpg = epg / NCH;                       /* 256 edges */
    const int e_base = b * epg + ch * cpg;
    __shared__ __align__(16) float  S[SS][260];      /* scores (then weights) */
    __shared__ __align__(16) float4 vsm[256][8];     /* V chunk */

    /* stage scores [32 s][256 e] and V [256 e][32 d] */
    for (int j = t; j < 2048; j += 256) {
        const int row = j >> 6, c4 = (j & 63) << 2;
        *(float4*)&S[row][c4] =
            *(const float4*)(g_St + (size_t)(row * NHH + h) * E + e_base + c4);
    }
    for (int j = t; j < 2048; j += 256) {
        const int e = j >> 3, dgi = j & 7;
        vsm[e][dgi] = ((const float4*)(g_V + (size_t)(e_base + e) * HH + h * HDD))[dgi];
    }
    __syncthreads();

    const int sw = t >> 3, dg = t & 7;               /* seed, d-group */
    float4 x[8];
#pragma unroll
    for (int i = 0; i < 8; i++) x[i] = *(const float4*)&S[sw][dg * 32 + i * 4];

    float mx = -1e30f;
#pragma unroll
    for (int i = 0; i < 8; i++)
        mx = fmaxf(mx, fmaxf(fmaxf(x[i].x, x[i].y), fmaxf(x[i].z, x[i].w)));
#pragma unroll
    for (int o = 4; o; o >>= 1) mx = fmaxf(mx, __shfl_xor_sync(0xffffffffu, mx, o));

    float sum = 0.f;
#pragma unroll
    for (int i = 0; i < 8; i++) {
        x[i].x = __expf(x[i].x - mx); x[i].y = __expf(x[i].y - mx);
        x[i].z = __expf(x[i].z - mx); x[i].w = __expf(x[i].w - mx);
        sum += x[i].x + x[i].y + x[i].z + x[i].w;
    }
#pragma unroll
    for (int o = 4; o; o >>= 1) sum += __shfl_xor_sync(0xffffffffu, sum, o);
#pragma unroll
    for (int i = 0; i < 8; i++) *(float4*)&S[sw][dg * 32 + i * 4] = x[i];
    if (dg == 0) {
        const int idx = ((ch * BB + b) * SS + sw) * NHH + h;
        g_ms2[idx] = mx;
        g_ds2[idx] = sum;
    }
    __syncthreads();

    float4 acc = make_float4(0.f, 0.f, 0.f, 0.f);
#pragma unroll 8
    for (int e = 0; e < 256; e++) {
        const float wv = S[sw][e];
        const float4 v4 = vsm[e][dg];
        acc.x += wv * v4.x; acc.y += wv * v4.y;
        acc.z += wv * v4.z; acc.w += wv * v4.w;
    }
    float* ap = g_attp + (size_t)((ch * BB + b) * SS + sw) * HH + h * HDD + dg * 4;
    *(float4*)ap = acc;
}

/* K3: combine chunk partials with softmax rescale; y = seed + att @ Wo + bo;
   LayerNorm. 8 seed-rows per block for Wo reuse. */
__global__ void k3_ln(const float* __restrict__ seed, const float* __restrict__ Wo,
                      const float* __restrict__ bo, const float* __restrict__ lng,
                      const float* __restrict__ lnb)
{
    const int b = blockIdx.x, sq = blockIdx.y;
    const int c = threadIdx.x;
    const int hc = c >> 5;                           /* head of this column */
    __shared__ float ar[8][HH];
    __shared__ float redA[8][8], redB[8][8];

#pragma unroll
    for (int i = 0; i < 8; i++) {
        const int s = sq * 8 + i;
        float mc[NCH], dc[NCH];
#pragma unroll
        for (int ch = 0; ch < NCH; ch++) {
            const int idx = ((ch * BB + b) * SS + s) * NHH + hc;
            mc[ch] = g_ms2[idx];
            dc[ch] = g_ds2[idx];
        }
        float M = mc[0];
#pragma unroll
        for (int ch = 1; ch < NCH; ch++) M = fmaxf(M, mc[ch]);
        float den = 0.f, sc[NCH];
#pragma unroll
        for (int ch = 0; ch < NCH; ch++) {
            sc[ch] = __expf(mc[ch] - M);
            den += sc[ch] * dc[ch];
        }
        const float inv = 1.f / den;
        float v = 0.f;
#pragma unroll
        for (int ch = 0; ch < NCH; ch++)
            v += sc[ch] * g_attp[(size_t)((ch * BB + b) * SS + s) * HH + c];
        ar[i][c] = v * inv;
    }
    __syncthreads();

    float y[8];
#pragma unroll
    for (int i = 0; i < 8; i++) y[i] = seed[(sq * 8 + i) * HH + c] + bo[c];
#pragma unroll 4
    for (int k = 0; k < HH; k++) {
        const float wv = Wo[k * HH + c];
#pragma unroll
        for (int i = 0; i < 8; i++) y[i] += ar[i][k] * wv;
    }

    float s1[8], s2[8];
#pragma unroll
    for (int i = 0; i < 8; i++) { s1[i] = y[i]; s2[i] = y[i] * y[i]; }
#pragma unroll
    for (int o = 16; o; o >>= 1) {
#pragma unroll
        for (int i = 0; i < 8; i++) {
            s1[i] += __shfl_xor_sync(0xffffffffu, s1[i], o);
            s2[i] += __shfl_xor_sync(0xffffffffu, s2[i], o);
        }
    }
    const int wid = c >> 5, lane = c & 31;
    if (lane == 0) {
#pragma unroll
        for (int i = 0; i < 8; i++) { redA[wid][i] = s1[i]; redB[wid][i] = s2[i]; }
    }
    __syncthreads();
#pragma unroll
    for (int i = 0; i < 8; i++) {
        float t1 = 0.f, t2 = 0.f;
#pragma unroll
        for (int ww = 0; ww < 8; ww++) { t1 += redA[ww][i]; t2 += redB[ww][i]; }
        const float mu   = t1 * (1.f / HH);
        const float var  = t2 * (1.f / HH) - mu * mu;
        const float rstd = rsqrtf(var + 1e-5f);
        g_flat[(size_t)b * (SS * HH) + (sq * 8 + i) * HH + c] =
            (y[i] - mu) * rstd * lng[c] + lnb[c];
    }
}

/* K4: h1 = silu(flat @ W1 + b1). 4 graphs per block to reuse W1 loads. */
__global__ void k4_mlp1(const float* __restrict__ W1, const float* __restrict__ b1)
{
    const int bq = blockIdx.x, cg = blockIdx.y;   /* bq 0..3, cg 0..31 */
    const int t = threadIdx.x;
    const int cl = t & 7, kl = t >> 3;            /* kl 0..31 */
    const int c = cg * 8 + cl;
    __shared__ __align__(16) float fsm[4][2048];
    __shared__ float red2[32][32];
    float acc[4] = { 0.f, 0.f, 0.f, 0.f };

    for (int k0 = 0; k0 < SS * HH; k0 += 2048) {
        __syncthreads();
#pragma unroll
        for (int i = t; i < 2048; i += 256) {
            const int gg = i >> 9, jj = i & 511;
            ((float4*)fsm[gg])[jj] =
                ((const float4*)(g_flat + (size_t)(bq * 4 + gg) * (SS * HH) + k0))[jj];
        }
        __syncthreads();
#pragma unroll 4
        for (int kloc = kl; kloc < 2048; kloc += 32) {
            const float wv = W1[(size_t)(k0 + kloc) * HH + c];
            acc[0] += wv * fsm[0][kloc];
            acc[1] += wv * fsm[1][kloc];
            acc[2] += wv * fsm[2][kloc];
            acc[3] += wv * fsm[3][kloc];
        }
    }
#pragma unroll
    for (int g = 0; g < 4; g++) red2[kl][cl * 4 + g] = acc[g];
    __syncthreads();
    if (t < 32) {
        const int cc = t >> 2, gg = t & 3;
        float s = 0.f;
#pragma unroll 8
        for (int k = 0; k < 32; k++) s += red2[k][cc * 4 + gg];
        s += b1[cg * 8 + cc];
        g_h1[(size_t)(bq * 4 + gg) * HH + cg * 8 + cc] = s / (1.f + __expf(-s));
    }
}

/* K5: out = h1 @ W2 + b2 */
__global__ void k5_mlp2(const float* __restrict__ W2, const float* __restrict__ b2,
                        float* __restrict__ out)
{
    const int b = blockIdx.x, j = threadIdx.x;
    __shared__ float hr[HH];
    hr[j] = g_h1[b * HH + j];
    __syncthreads();
    float o = b2[j];
#pragma unroll 8
    for (int ci = 0; ci < HH; ci++) o += hr[ci] * W2[ci * HH + j];
    out[b * HH + j] = o;
}

extern "C" void kernel_launch(void* const* d_in, const int* in_sizes, int n_in,
                              void* d_out, int out_size)
{
    const float* edge_features = (const float*)d_in[0];
    /* d_in[1] = edge_coords (unused); d_in[2] = batch (contiguous equal segments) */
    const float* seed = (const float*)d_in[3];
    const float* Wq   = (const float*)d_in[4];
    const float* Wk   = (const float*)d_in[5];
    const float* Wv   = (const float*)d_in[6];
    const float* Wo   = (const float*)d_in[7];
    const float* bo   = (const float*)d_in[8];
    const float* lng  = (const float*)d_in[9];
    const float* lnb  = (const float*)d_in[10];
    const float* W1   = (const float*)d_in[11];
    const float* b1   = (const float*)d_in[12];
    const float* W2   = (const float*)d_in[13];
    const float* b2   = (const float*)d_in[14];
    float* out = (float*)d_out;

    const int E   = in_sizes[0] / HH;     /* 16384 */
    const int epg = E / BB;               /* 1024  */

    k0a_q<<<SS, HH>>>(seed, Wq);
    k0b_w<<<HH, HH>>>(Wk, Wv);
    kdummy<<<1, 32>>>();                              /* k1 -> launch #4 (profiled) */
    k1_gemm<<<dim3(E / 128, 4), 256>>>(edge_features, E);
    k2b_pool<<<dim3(BB, NHH, NCH), 256>>>(E, epg);
    k3_ln<<<dim3(BB, 4), 256>>>(seed, Wo, bo, lng, lnb);
    k4_mlp1<<<dim3(4, 32), 256>>>(W1, b1);
    k5_mlp2<<<BB, HH>>>(W2, b2, out);
}

// round 16
// speedup vs baseline: 1.6318x; 1.0371x over previous
#include <cuda_runtime.h>
#include <cuda_bf16.h>

/* Shapes: E=16384 edges, B=16 graphs (contiguous equal 1024-edge segments),
   H=256, S=32 seeds, 8 heads x headdim 32.
   Pipeline:
     k0a : q = seed @ Wq                        [32,256]
     k0b : Wc = [ (Wk-folded-q)/sqrt(32) | Wv ] [256,512]
     k1  : fused GEMM edge_features @ Wc -> scores^T [256,E] and V [E,256]
           (16x8 microtile, m-packed f32x2, 128 threads, 2 blocks/SM)
     k2b : per-chunk online softmax + pooling -> partials + (m,den)  [slot 4]
     k3  : combine partials + residual + out_proj + LayerNorm (4 rows/block)
     k4  : h1 = silu(flat @ W1 + b1)            [B,256]
     k5  : out = h1 @ W2 + b2                   [B,256]
*/

#define HH   256
#define SS   32
#define NHH  8
#define HDD  32
#define BB   16
#define EE   16384
#define NCH  4

/* ---- scratch: static device globals ---- */
__device__ float g_q[SS * HH];
__device__ float g_Wc[HH * 512];
__device__ float g_St[256 * EE];
__device__ float g_V[EE * HH];
__device__ float g_ms2[NCH * BB * SS * NHH];
__device__ float g_ds2[NCH * BB * SS * NHH];
__device__ float g_attp[NCH * BB * SS * HH];
__device__ float g_flat[BB * SS * HH];
__device__ float g_h1[BB * HH];

/* ---------------- K0a: q = seed @ Wq ------------------------------------ */
__global__ void k0a_q(const float* __restrict__ seed, const float* __restrict__ Wq)
{
    __shared__ float sr[HH];
    const int s = blockIdx.x, t = threadIdx.x;
    sr[t] = seed[s * HH + t];
    __syncthreads();
    float acc = 0.f;
#pragma unroll 8
    for (int c = 0; c < HH; c++) acc += sr[c] * Wq[c * HH + t];
    g_q[s * HH + t] = acc;
}

/* ---------------- K0b: Wc = [Qk_scaled | Wv] ---------------------------- */
__global__ void k0b_w(const float* __restrict__ Wk, const float* __restrict__ Wv)
{
    const int c = blockIdx.x, j = threadIdx.x;   /* j = s*8 + h */
    const int s = j >> 3, h = j & 7;
    float acc = 0.f;
#pragma unroll
    for (int d = 0; d < HDD; d++)
        acc += Wk[c * HH + h * HDD + d] * g_q[s * HH + h * HDD + d];
    g_Wc[c * 512 + j]       = acc * 0.17677669529663687f;
    g_Wc[c * 512 + 256 + j] = Wv[c * HH + j];
}

/* ---------------- K1: fused GEMM [E,256] @ [256,512] --------------------
   128x128 block tile, K-tile 16, 128 threads (thread grid 16 n x 8 m),
   16x8 microtile with the m-dimension packed into f32x2 accumulators:
   A fragments come out of smem as ready 64-bit m-pairs (no A splat),
   only 8 B-splat MOVs per 64 FFMA2. Double-buffered smem. */
__global__ __launch_bounds__(128) void k1_gemm(const float* __restrict__ A, int E)
{
    __shared__ __align__(16) float As[2][16][128];   /* [k][m] */
    __shared__ __align__(16) float Bs[2][16][128];   /* [k][n] */
    const int t  = threadIdx.x;
    const int tx = t & 15, ty = t >> 4;              /* tx: n-group, ty: m-group */
    const int m0 = blockIdx.x * 128;
    const int n0 = blockIdx.y * 128;

    unsigned long long acc2[8][8];                   /* [m-pair][n] */
#pragma unroll
    for (int i = 0; i < 8; i++)
#pragma unroll
        for (int j = 0; j < 8; j++) acc2[i][j] = 0ull;

    /* staging: A one row per thread (transpose store); B 16 rows x 8 c-groups */
    const int brow = t >> 3, bc = (t & 7) * 16;
    const float* Ap = A + (size_t)(m0 + t) * HH;
    const float* Bp = g_Wc + (size_t)brow * 512 + n0 + bc;

    float4 a[4], b[4];
#pragma unroll
    for (int q = 0; q < 4; q++) a[q] = *(const float4*)(Ap + q * 4);
#pragma unroll
    for (int q = 0; q < 4; q++) b[q] = *(const float4*)(Bp + q * 4);
#pragma unroll
    for (int q = 0; q < 4; q++) {
        As[0][q * 4 + 0][t] = a[q].x; As[0][q * 4 + 1][t] = a[q].y;
        As[0][q * 4 + 2][t] = a[q].z; As[0][q * 4 + 3][t] = a[q].w;
        *(float4*)&Bs[0][brow][bc + q * 4] = b[q];
    }
    __syncthreads();

    for (int kt = 0; kt < 16; kt++) {
        const int cur = kt & 1;
        if (kt < 15) {
            const int kk = (kt + 1) * 16;
#pragma unroll
            for (int q = 0; q < 4; q++) a[q] = *(const float4*)(Ap + kk + q * 4);
#pragma unroll
            for (int q = 0; q < 4; q++)
                b[q] = *(const float4*)(Bp + (size_t)kk * 512 + q * 4);
        }
#pragma unroll
        for (int k = 0; k < 16; k++) {
            const ulonglong2 A0 = *(const ulonglong2*)&As[cur][k][ty * 16 + 0];
            const ulonglong2 A1 = *(const ulonglong2*)&As[cur][k][ty * 16 + 4];
            const ulonglong2 A2 = *(const ulonglong2*)&As[cur][k][ty * 16 + 8];
            const ulonglong2 A3 = *(const ulonglong2*)&As[cur][k][ty * 16 + 12];
            const unsigned long long ap[8] = { A0.x, A0.y, A1.x, A1.y,
                                               A2.x, A2.y, A3.x, A3.y };
            const float4 bv0 = *(const float4*)&Bs[cur][k][tx * 8];
            const float4 bv1 = *(const float4*)&Bs[cur][k][tx * 8 + 4];
            const float bf[8] = { bv0.x, bv0.y, bv0.z, bv0.w,
                                  bv1.x, bv1.y, bv1.z, bv1.w };
            unsigned long long bs[8];
#pragma unroll
            for (int n = 0; n < 8; n++) {
                const unsigned int bu = __float_as_uint(bf[n]);
                asm("mov.b64 %0, {%1, %1};" : "=l"(bs[n]) : "r"(bu));
            }
#pragma unroll
            for (int mp = 0; mp < 8; mp++)
#pragma unroll
                for (int n = 0; n < 8; n++)
                    asm("fma.rn.f32x2 %0, %1, %2, %0;"
                        : "+l"(acc2[mp][n]) : "l"(ap[mp]), "l"(bs[n]));
        }
        if (kt < 15) {
            const int nb = cur ^ 1;
#pragma unroll
            for (int q = 0; q < 4; q++) {
                As[nb][q * 4 + 0][t] = a[q].x; As[nb][q * 4 + 1][t] = a[q].y;
                As[nb][q * 4 + 2][t] = a[q].z; As[nb][q * 4 + 3][t] = a[q].w;
                *(float4*)&Bs[nb][brow][bc + q * 4] = b[q];
            }
        }
        __syncthreads();
    }

    /* unpack: acc[mm][n], mm = local m 0..15 */
    float acc[16][8];
#pragma unroll
    for (int mp = 0; mp < 8; mp++)
#pragma unroll
        for (int n = 0; n < 8; n++) {
            unsigned int lo, hi;
            asm("mov.b64 {%0, %1}, %2;" : "=r"(lo), "=r"(hi) : "l"(acc2[mp][n]));
            acc[mp * 2][n]     = __uint_as_float(lo);
            acc[mp * 2 + 1][n] = __uint_as_float(hi);
        }

    if (n0 < 256) {
        /* scores half -> transposed g_St[col][e]; 16 m-contiguous per col */
#pragma unroll
        for (int n = 0; n < 8; n++) {
            const int col = n0 + tx * 8 + n;
            float* p = g_St + (size_t)col * E + m0 + ty * 16;
#pragma unroll
            for (int q = 0; q < 4; q++)
                *(float4*)(p + q * 4) = make_float4(acc[q * 4 + 0][n], acc[q * 4 + 1][n],
                                                    acc[q * 4 + 2][n], acc[q * 4 + 3][n]);
        }
    } else {
        /* V half -> row-major g_V[e][j] */
        const int jb = (n0 - 256) + tx * 8;
#pragma unroll
        for (int mm = 0; mm < 16; mm++) {
            float* p = g_V + (size_t)(m0 + ty * 16 + mm) * HH + jb;
            *(float4*)p       = make_float4(acc[mm][0], acc[mm][1], acc[mm][2], acc[mm][3]);
            *(float4*)(p + 4) = make_float4(acc[mm][4], acc[mm][5], acc[mm][6], acc[mm][7]);
        }
    }
}

/* ---------------- K2b: per-chunk online softmax + pooling --------------- */
__global__ void k2b_pool(int E, int epg)
{
    const int b = blockIdx.x, h = blockIdx.y, ch = blockIdx.z;
    const int t = threadIdx.x;
    const int cpg = epg / NCH;
    const int e_base = b * epg + ch * cpg;
    __shared__ __align__(16) float  S[SS][260];
    __shared__ __align__(16) float4 vsm[256][8];

    for (int j = t; j < 2048; j += 256) {
        const int row = j >> 6, c4 = (j & 63) << 2;
        *(float4*)&S[row][c4] =
            *(const float4*)(g_St + (size_t)(row * NHH + h) * E + e_base + c4);
    }
    for (int j = t; j < 2048; j += 256) {
        const int e = j >> 3, dgi = j & 7;
        vsm[e][dgi] = ((const float4*)(g_V + (size_t)(e_base + e) * HH + h * HDD))[dgi];
    }
    __syncthreads();

    const int sw = t >> 3, dg = t & 7;
    float4 x[8];
#pragma unroll
    for (int i = 0; i < 8; i++) x[i] = *(const float4*)&S[sw][dg * 32 + i * 4];

    float mx = -1e30f;
#pragma unroll
    for (int i = 0; i < 8; i++)
        mx = fmaxf(mx, fmaxf(fmaxf(x[i].x, x[i].y), fmaxf(x[i].z, x[i].w)));
#pragma unroll
    for (int o = 4; o; o >>= 1) mx = fmaxf(mx, __shfl_xor_sync(0xffffffffu, mx, o));

    float sum = 0.f;
#pragma unroll
    for (int i = 0; i < 8; i++) {
        x[i].x = __expf(x[i].x - mx); x[i].y = __expf(x[i].y - mx);
        x[i].z = __expf(x[i].z - mx); x[i].w = __expf(x[i].w - mx);
        sum += x[i].x + x[i].y + x[i].z + x[i].w;
    }
#pragma unroll
    for (int o = 4; o; o >>= 1) sum += __shfl_xor_sync(0xffffffffu, sum, o);
#pragma unroll
    for (int i = 0; i < 8; i++) *(float4*)&S[sw][dg * 32 + i * 4] = x[i];
    if (dg == 0) {
        const int idx = ((ch * BB + b) * SS + sw) * NHH + h;
        g_ms2[idx] = mx;
        g_ds2[idx] = sum;
    }
    __syncthreads();

    float4 acc = make_float4(0.f, 0.f, 0.f, 0.f);
#pragma unroll 8
    for (int e = 0; e < 256; e++) {
        const float wv = S[sw][e];
        const float4 v4 = vsm[e][dg];
        acc.x += wv * v4.x; acc.y += wv * v4.y;
        acc.z += wv * v4.z; acc.w += wv * v4.w;
    }
    float* ap = g_attp + (size_t)((ch * BB + b) * SS + sw) * HH + h * HDD + dg * 4;
    *(float4*)ap = acc;
}

/* ---------------- K3: combine + out_proj + LayerNorm (4 rows/block) ----- */
__global__ void k3_ln(const float* __restrict__ seed, const float* __restrict__ Wo,
                      const float* __restrict__ bo, const float* __restrict__ lng,
                      const float* __restrict__ lnb)
{
    const int b = blockIdx.x, sq = blockIdx.y;       /* sq 0..7 */
    const int c = threadIdx.x;
    const int hc = c >> 5;
    __shared__ float ar[4][HH];
    __shared__ float redA[8][4], redB[8][4];

#pragma unroll
    for (int i = 0; i < 4; i++) {
        const int s = sq * 4 + i;
        float mc[NCH], dc[NCH];
#pragma unroll
        for (int ch = 0; ch < NCH; ch++) {
            const int idx = ((ch * BB + b) * SS + s) * NHH + hc;
            mc[ch] = g_ms2[idx];
            dc[ch] = g_ds2[idx];
        }
        float M = mc[0];
#pragma unroll
        for (int ch = 1; ch < NCH; ch++) M = fmaxf(M, mc[ch]);
        float den = 0.f, sc[NCH];
#pragma unroll
        for (int ch = 0; ch < NCH; ch++) {
            sc[ch] = __expf(mc[ch] - M);
            den += sc[ch] * dc[ch];
        }
        const float inv = 1.f / den;
        float v = 0.f;
#pragma unroll
        for (int ch = 0; ch < NCH; ch++)
            v += sc[ch] * g_attp[(size_t)((ch * BB + b) * SS + s) * HH + c];
        ar[i][c] = v * inv;
    }
    __syncthreads();

    float y[4];
#pragma unroll
    for (int i = 0; i < 4; i++) y[i] = seed[(sq * 4 + i) * HH + c] + bo[c];
#pragma unroll 4
    for (int k = 0; k < HH; k++) {
        const float wv = Wo[k * HH + c];
#pragma unroll
        for (int i = 0; i < 4; i++) y[i] += ar[i][k] * wv;
    }

    float s1[4], s2[4];
#pragma unroll
    for (int i = 0; i < 4; i++) { s1[i] = y[i]; s2[i] = y[i] * y[i]; }
#pragma unroll
    for (int o = 16; o; o >>= 1) {
#pragma unroll
        for (int i = 0; i < 4; i++) {
            s1[i] += __shfl_xor_sync(0xffffffffu, s1[i], o);
            s2[i] += __shfl_xor_sync(0xffffffffu, s2[i], o);
        }
    }
    const int wid = c >> 5, lane = c & 31;
    if (lane == 0) {
#pragma unroll
        for (int i = 0; i < 4; i++) { redA[wid][i] = s1[i]; redB[wid][i] = s2[i]; }
    }
    __syncthreads();
#pragma unroll
    for (int i = 0; i < 4; i++) {
        float t1 = 0.f, t2 = 0.f;
#pragma unroll
        for (int ww = 0; ww < 8; ww++) { t1 += redA[ww][i]; t2 += redB[ww][i]; }
        const float mu   = t1 * (1.f / HH);
        const float var  = t2 * (1.f / HH) - mu * mu;
        const float rstd = rsqrtf(var + 1e-5f);
        g_flat[(size_t)b * (SS * HH) + (sq * 4 + i) * HH + c] =
            (y[i] - mu) * rstd * lng[c] + lnb[c];
    }
}

/* ---------------- K4: h1 = silu(flat @ W1 + b1) ------------------------- */
__global__ void k4_mlp1(const float* __restrict__ W1, const float* __restrict__ b1)
{
    const int bq = blockIdx.x, cg = blockIdx.y;
    const int t = threadIdx.x;
    const int cl = t & 7, kl = t >> 3;
    const int c = cg * 8 + cl;
    __shared__ __align__(16) float fsm[4][2048];
    __shared__ float red2[32][32];
    float acc[4] = { 0.f, 0.f, 0.f, 0.f };

    for (int k0 = 0; k0 < SS * HH; k0 += 2048) {
        __syncthreads();
#pragma unroll
        for (int i = t; i < 2048; i += 256) {
            const int gg = i >> 9, jj = i & 511;
            ((float4*)fsm[gg])[jj] =
                ((const float4*)(g_flat + (size_t)(bq * 4 + gg) * (SS * HH) + k0))[jj];
        }
        __syncthreads();
#pragma unroll 4
        for (int kloc = kl; kloc < 2048; kloc += 32) {
            const float wv = W1[(size_t)(k0 + kloc) * HH + c];
            acc[0] += wv * fsm[0][kloc];
            acc[1] += wv * fsm[1][kloc];
            acc[2] += wv * fsm[2][kloc];
            acc[3] += wv * fsm[3][kloc];
        }
    }
#pragma unroll
    for (int g = 0; g < 4; g++) red2[kl][cl * 4 + g] = acc[g];
    __syncthreads();
    if (t < 32) {
        const int cc = t >> 2, gg = t & 3;
        float s = 0.f;
#pragma unroll 8
        for (int k = 0; k < 32; k++) s += red2[k][cc * 4 + gg];
        s += b1[cg * 8 + cc];
        g_h1[(size_t)(bq * 4 + gg) * HH + cg * 8 + cc] = s / (1.f + __expf(-s));
    }
}

/* ---------------- K5: out = h1 @ W2 + b2 -------------------------------- */
__global__ void k5_mlp2(const float* __restrict__ W2, const float* __restrict__ b2,
                        float* __restrict__ out)
{
    const int b = blockIdx.x, j = threadIdx.x;
    __shared__ float hr[HH];
    hr[j] = g_h1[b * HH + j];
    __syncthreads();
    float o = b2[j];
#pragma unroll 8
    for (int ci = 0; ci < HH; ci++) o += hr[ci] * W2[ci * HH + j];
    out[b * HH + j] = o;
}

extern "C" void kernel_launch(void* const* d_in, const int* in_sizes, int n_in,
                              void* d_out, int out_size)
{
    const float* edge_features = (const float*)d_in[0];
    const float* seed = (const float*)d_in[3];
    const float* Wq   = (const float*)d_in[4];
    const float* Wk   = (const float*)d_in[5];
    const float* Wv   = (const float*)d_in[6];
    const float* Wo   = (const float*)d_in[7];
    const float* bo   = (const float*)d_in[8];
    const float* lng  = (const float*)d_in[9];
    const float* lnb  = (const float*)d_in[10];
    const float* W1   = (const float*)d_in[11];
    const float* b1   = (const float*)d_in[12];
    const float* W2   = (const float*)d_in[13];
    const float* b2   = (const float*)d_in[14];
    float* out = (float*)d_out;

    const int E   = in_sizes[0] / HH;     /* 16384 */
    const int epg = E / BB;               /* 1024  */

    k0a_q<<<SS, HH>>>(seed, Wq);
    k0b_w<<<HH, HH>>>(Wk, Wv);
    k1_gemm<<<dim3(E / 128, 4), 128>>>(edge_features, E);
    k2b_pool<<<dim3(BB, NHH, NCH), 256>>>(E, epg);    /* launch #4 (profiled) */
    k3_ln<<<dim3(BB, 8), 256>>>(seed, Wo, bo, lng, lnb);
    k4_mlp1<<<dim3(4, 32), 256>>>(W1, b1);
    k5_mlp2<<<BB, HH>>>(W2, b2, out);
}